// round 14
// baseline (speedup 1.0000x reference)
#include <cuda_runtime.h>
#include <cuda_fp16.h>
#include <cstdint>

// ---------------------------------------------------------------------------
// Problem constants
// ---------------------------------------------------------------------------
#define GB 4
#define GL 4096
#define GD 2048
#define GN_STATE 16
#define GM (GB*GL)          // 16384
#define GK GD               // 2048
#define DT_MIN 1e-4f
#define PLANE ((size_t)GM * GD)
#define NCHAN (GB * GD)     // 8192 channels
#define CCH 16              // scan chunks
#define TCH (GL / CCH)      // 256 steps per chunk

// Projections stored TRANSPOSED: [z][d][m]
__device__ float g_proj[3 * PLANE];
// Transposed fp16 weights: [z][d][k]
__device__ __half g_wth[(size_t)3 * GD * GK];
// fp16 u, GEMM orientation [m][k]
__device__ __half g_uph[PLANE];
// fp32 u, scan orientation [d][m]
__device__ float g_ut[PLANE];
// Scan chunk carries
__device__ float g_P [(CCH - 1) * NCHAN * GN_STATE];
__device__ float g_S [(CCH - 1) * NCHAN * GN_STATE];
__device__ float g_x0[CCH * NCHAN * GN_STATE];

__device__ __forceinline__ uint32_t smem_u32(const void* p) {
    uint32_t a;
    asm("{ .reg .u64 t; cvta.to.shared.u64 t, %1; cvt.u32.u64 %0, t; }" : "=r"(a) : "l"(p));
    return a;
}
__device__ __forceinline__ float softplus_f(float x) {
    return log1pf(expf(-fabsf(x))) + fmaxf(x, 0.0f);
}
__device__ __forceinline__ void mma_f16(float c[4], const uint32_t a[4],
                                        uint32_t b0, uint32_t b1) {
    asm volatile(
        "mma.sync.aligned.m16n8k16.row.col.f32.f16.f16.f32 "
        "{%0,%1,%2,%3}, {%4,%5,%6,%7}, {%8,%9}, {%0,%1,%2,%3};\n"
        : "+f"(c[0]), "+f"(c[1]), "+f"(c[2]), "+f"(c[3])
        : "r"(a[0]), "r"(a[1]), "r"(a[2]), "r"(a[3]), "r"(b0), "r"(b1));
}
__device__ __forceinline__ void cp_async16(uint32_t dst, const void* src) {
    asm volatile("cp.async.cg.shared.global [%0], [%1], 16;" :: "r"(dst), "l"(src));
}
__device__ __forceinline__ void ldsm_x4(uint32_t& r0, uint32_t& r1,
                                        uint32_t& r2, uint32_t& r3, uint32_t a) {
    asm volatile("ldmatrix.sync.aligned.m8n8.x4.shared.b16 {%0,%1,%2,%3}, [%4];"
                 : "=r"(r0), "=r"(r1), "=r"(r2), "=r"(r3) : "r"(a));
}
// Packed exp2 on two states at once (single MUFU for both halves).
__device__ __forceinline__ float2 ex2_pair(float a0, float a1) {
    __half2 h = h2exp2(__floats2half2_rn(a0, a1));
    return __half22float2(h);
}

// ---------------------------------------------------------------------------
// Prep: weight transpose + fp16 convert. g_wth[z][d][k] = half(W_z[k][d])
// ---------------------------------------------------------------------------
__global__ void wtrans_kernel(const float* __restrict__ Wdt,
                              const float* __restrict__ Wb,
                              const float* __restrict__ Wc) {
    __shared__ float t[32][33];
    const int z = blockIdx.z;
    const float* __restrict__ W = (z == 0) ? Wdt : ((z == 1) ? Wb : Wc);
    __half* __restrict__ out = g_wth + (size_t)z * GD * GK;
    const int k0 = blockIdx.x * 32, d0 = blockIdx.y * 32;
    for (int i = threadIdx.y; i < 32; i += 8)
        t[i][threadIdx.x] = W[(size_t)(k0 + i) * GD + d0 + threadIdx.x];
    __syncthreads();
    for (int i = threadIdx.y; i < 32; i += 8)
        out[(size_t)(d0 + i) * GK + k0 + threadIdx.x] =
            __float2half_rn(t[threadIdx.x][i]);
}

// ---------------------------------------------------------------------------
// Prep: u -> fp16 [m][k] for GEMM, fp32 transposed [d][m] for scan.
// ---------------------------------------------------------------------------
__global__ void uprep_kernel(const float* __restrict__ u) {
    __shared__ float t[32][33];
    const int d0 = blockIdx.x * 32, m0 = blockIdx.y * 32;
    for (int i = threadIdx.y; i < 32; i += 8) {
        float v = u[(size_t)(m0 + i) * GD + d0 + threadIdx.x];
        t[i][threadIdx.x] = v;
        g_uph[(size_t)(m0 + i) * GD + d0 + threadIdx.x] = __float2half_rn(v);
    }
    __syncthreads();
    for (int i = threadIdx.y; i < 32; i += 8)
        g_ut[(size_t)(d0 + i) * GM + m0 + threadIdx.x] = t[threadIdx.x][i];
}

// ---------------------------------------------------------------------------
// Pipelined fp16 GEMM with ldmatrix fragments (R11 configuration).
// Block 128(d=M) x 128(m=N), 256 threads (8 warps: 4 M x 2 N), warp 32x64.
// K-chunk 64 halves (4 x m16n8k16). 3-stage cp.async, 110,592 B smem,
// 2 blocks/SM. Row pitch 144 B -> conflict-free LDSM (offsets 16i mod 128).
// ---------------------------------------------------------------------------
#define KCH 64
#define PITCHB 144                    // 64 halves (128 B) + 16 B pad
#define A_BYTES (128 * PITCHB)        // 18432
#define B_BYTES (128 * PITCHB)        // 18432
#define STAGE_BYTES (A_BYTES + B_BYTES)   // 36864
#define GEMM_SMEM (3 * STAGE_BYTES)   // 110592
#define NCH (GK / KCH)                // 32

__global__ void __launch_bounds__(256, 2)
gemm_tc_kernel(const float* __restrict__ bdt, const float* __restrict__ bb,
               const float* __restrict__ bc) {
    extern __shared__ char smem[];

    const int tid = threadIdx.x;
    const int lane = tid & 31;
    const int warp = tid >> 5;
    const int z    = blockIdx.x >> 4;
    const int bd   = (blockIdx.x & 15) * 128;
    const int bm   = blockIdx.y * 128;
    const __half* __restrict__ W = g_wth + (size_t)z * GD * GK;
    const float* __restrict__ bias = (z == 0) ? bdt : ((z == 1) ? bb : bc);
    float* __restrict__ out = g_proj + (size_t)z * PLANE;

    const int wm = (warp & 3) * 32;     // 4 warps along M (d)
    const int wn = (warp >> 2) * 64;    // 2 warps along N (m)
    const int g  = lane >> 2;
    const int th = lane & 3;

    // Per-lane LDSM row/col offsets (loop-invariant).
    const int q = lane >> 3, i8 = lane & 7;
    const int a_row = wm + (q & 1) * 8 + i8;
    const int a_kb  = (q >> 1) * 16;
    const int b_rowo = (q >> 1) * 8 + i8;
    const int b_kb   = (q & 1) * 16;

    auto load_stage = [&](int c, int buf) {
        const int k0 = c * KCH;
        const uint32_t aB = smem_u32(smem + buf * STAGE_BYTES);
        const uint32_t bB = aB + A_BYTES;
        #pragma unroll
        for (int i = 0; i < 4; i++) {
            int lin = tid + i * 256;
            int row = lin >> 3, ch = lin & 7;
            cp_async16(aB + row * PITCHB + ch * 16,
                       W + (size_t)(bd + row) * GK + k0 + ch * 8);
        }
        #pragma unroll
        for (int i = 0; i < 4; i++) {
            int lin = tid + i * 256;
            int row = lin >> 3, ch = lin & 7;
            cp_async16(bB + row * PITCHB + ch * 16,
                       g_uph + (size_t)(bm + row) * GK + k0 + ch * 8);
        }
        asm volatile("cp.async.commit_group;" ::: "memory");
    };

    float acc[2][8][4];
    #pragma unroll
    for (int i = 0; i < 2; i++)
        #pragma unroll
        for (int j = 0; j < 8; j++)
            #pragma unroll
            for (int k = 0; k < 4; k++) acc[i][j][k] = 0.0f;

    load_stage(0, 0);
    load_stage(1, 1);

    for (int c = 0; c < NCH; c++) {
        const int buf = c % 3;
        if (c == NCH - 1)
            asm volatile("cp.async.wait_group 0;" ::: "memory");
        else
            asm volatile("cp.async.wait_group 1;" ::: "memory");
        __syncthreads();

        const uint32_t aS = smem_u32(smem + buf * STAGE_BYTES);
        const uint32_t bS = aS + A_BYTES;
        const uint32_t aLane = aS + a_row * PITCHB + a_kb;
        const uint32_t bLane = bS + (wn + b_rowo) * PITCHB + b_kb;

        #pragma unroll
        for (int kk = 0; kk < 4; kk++) {          // four m16n8k16 K-steps
            const uint32_t kb = kk * 32;
            uint32_t a[2][4];
            ldsm_x4(a[0][0], a[0][1], a[0][2], a[0][3], aLane + kb);
            ldsm_x4(a[1][0], a[1][1], a[1][2], a[1][3],
                    aLane + 16 * PITCHB + kb);
            uint32_t b[4][4];                      // [ntp][b0,b1 of nt, nt+1]
            #pragma unroll
            for (int ntp = 0; ntp < 4; ntp++)
                ldsm_x4(b[ntp][0], b[ntp][1], b[ntp][2], b[ntp][3],
                        bLane + (ntp * 16) * PITCHB + kb);
            #pragma unroll
            for (int ntp = 0; ntp < 4; ntp++) {
                mma_f16(acc[0][ntp * 2 + 0], a[0], b[ntp][0], b[ntp][1]);
                mma_f16(acc[1][ntp * 2 + 0], a[1], b[ntp][0], b[ntp][1]);
                mma_f16(acc[0][ntp * 2 + 1], a[0], b[ntp][2], b[ntp][3]);
                mma_f16(acc[1][ntp * 2 + 1], a[1], b[ntp][2], b[ntp][3]);
            }
        }
        if (c + 2 < NCH) load_stage(c + 2, (c + 2) % 3);
    }

    #pragma unroll
    for (int mt = 0; mt < 2; mt++) {
        #pragma unroll
        for (int e2 = 0; e2 < 2; e2++) {
            int r = bd + wm + mt * 16 + g + e2 * 8;
            float bv = bias[r];
            float* orow = out + (size_t)r * GM + bm;
            #pragma unroll
            for (int nt = 0; nt < 8; nt++) {
                int c0 = wn + nt * 8 + 2 * th;
                float2 v;
                v.x = acc[mt][nt][e2 * 2 + 0] + bv;
                v.y = acc[mt][nt][e2 * 2 + 1] + bv;
                if (z == 0) {
                    v.x = softplus_f(v.x) + DT_MIN;
                    v.y = softplus_f(v.y) + DT_MIN;
                }
                *reinterpret_cast<float2*>(orow + c0) = v;
            }
        }
    }
}

// ---------------------------------------------------------------------------
// Scan phase A: per (channel, chunk j<CCH-1) compute P[n] = prod Abar,
// S[n] = chunk-local state (x_start = 0). Thread = one channel, 16 states.
// Packed f16x2 exp2: 8 MUFU per step instead of 16.
// ---------------------------------------------------------------------------
__global__ void __launch_bounds__(128)
scanA_kernel(const float* __restrict__ a_raw, const float* __restrict__ B_base) {
    const int ch = blockIdx.x * 128 + threadIdx.x;
    const int j  = blockIdx.y;
    const int b = ch >> 11, d = ch & 2047;

    float kA[16], Bb[16], P[16], S[16];
    #pragma unroll
    for (int n = 0; n < 16; n++) {
        kA[n] = -softplus_f(a_raw[d * GN_STATE + n]) * 1.4426950408889634f;
        Bb[n] = B_base[d * GN_STATE + n];
        P[n] = 1.0f;
        S[n] = 0.0f;
    }

    const size_t sbase = (size_t)d * GM + (size_t)b * GL + (size_t)j * TCH;
    const float* __restrict__ pdt = g_proj + sbase;
    const float* __restrict__ pbv = g_proj + PLANE + sbase;
    const float* __restrict__ pu  = g_ut + sbase;

    auto step = [&](float dts, float bs, float us) {
        const float w = dts * bs * us;
        #pragma unroll
        for (int n = 0; n < 16; n += 2) {
            float2 ab = ex2_pair(dts * kA[n], dts * kA[n + 1]);
            P[n] *= ab.x;
            S[n] = fmaf(ab.x, S[n], w * Bb[n]);
            P[n + 1] *= ab.y;
            S[n + 1] = fmaf(ab.y, S[n + 1], w * Bb[n + 1]);
        }
    };

    for (int tt = 0; tt < TCH; tt += 4) {
        float4 d4 = *reinterpret_cast<const float4*>(pdt + tt);
        float4 b4 = *reinterpret_cast<const float4*>(pbv + tt);
        float4 u4 = *reinterpret_cast<const float4*>(pu + tt);
        step(d4.x, b4.x, u4.x);
        step(d4.y, b4.y, u4.y);
        step(d4.z, b4.z, u4.z);
        step(d4.w, b4.w, u4.w);
    }

    const int o = (j * NCHAN + ch) * GN_STATE;
    #pragma unroll
    for (int n = 0; n < 16; n++) {
        g_P[o + n] = P[n];
        g_S[o + n] = S[n];
    }
}

// ---------------------------------------------------------------------------
// Scan combine: x0(0)=0; x0(j)=S(j-1)+P(j-1)*x0(j-1)
// ---------------------------------------------------------------------------
__global__ void __launch_bounds__(256)
scanC_kernel() {
    const int id = blockIdx.x * 256 + threadIdx.x;   // 0 .. NCHAN*16-1
    float x = 0.0f;
    g_x0[id] = 0.0f;
    #pragma unroll
    for (int j = 1; j < CCH; j++) {
        const int o = (j - 1) * NCHAN * GN_STATE + id;
        x = g_S[o] + g_P[o] * x;
        g_x0[j * NCHAN * GN_STATE + id] = x;
    }
}

// ---------------------------------------------------------------------------
// Scan phase B: full walk per chunk with known x_start; emits y (+ carry).
// Packed f16x2 exp2.
// ---------------------------------------------------------------------------
__global__ void __launch_bounds__(128)
scanB_kernel(const float* __restrict__ a_raw, const float* __restrict__ B_base,
             const float* __restrict__ C_base, const float* __restrict__ Dv,
             float* __restrict__ carry, float* __restrict__ y) {
    const int ch = blockIdx.x * 128 + threadIdx.x;
    const int j  = blockIdx.y;
    const int b = ch >> 11, d = ch & 2047;

    float kA[16], Bb[16], Cb[16], x[16];
    #pragma unroll
    for (int n = 0; n < 16; n++) {
        kA[n] = -softplus_f(a_raw[d * GN_STATE + n]) * 1.4426950408889634f;
        Bb[n] = B_base[d * GN_STATE + n];
        Cb[n] = C_base[d * GN_STATE + n];
        x[n]  = g_x0[(j * NCHAN + ch) * GN_STATE + n];
    }
    const float Dd = Dv[d];

    const size_t sbase = (size_t)d * GM + (size_t)b * GL + (size_t)j * TCH;
    const float* __restrict__ pdt = g_proj + sbase;
    const float* __restrict__ pbv = g_proj + PLANE + sbase;
    const float* __restrict__ pcv = g_proj + 2 * PLANE + sbase;
    const float* __restrict__ pu  = g_ut + sbase;
    float* __restrict__ yb = y + ((size_t)b * GL + (size_t)j * TCH) * GD + d;

    auto step = [&](float dts, float bs, float cs, float us, int t) {
        const float w = dts * bs * us;
        float acc = 0.0f;
        #pragma unroll
        for (int n = 0; n < 16; n += 2) {
            float2 ab = ex2_pair(dts * kA[n], dts * kA[n + 1]);
            x[n] = fmaf(ab.x, x[n], w * Bb[n]);
            acc = fmaf(x[n], Cb[n], acc);
            x[n + 1] = fmaf(ab.y, x[n + 1], w * Bb[n + 1]);
            acc = fmaf(x[n + 1], Cb[n + 1], acc);
        }
        yb[(size_t)t * GD] = fmaf(cs, acc, Dd * us);
    };

    for (int tt = 0; tt < TCH; tt += 4) {
        float4 d4 = *reinterpret_cast<const float4*>(pdt + tt);
        float4 b4 = *reinterpret_cast<const float4*>(pbv + tt);
        float4 c4 = *reinterpret_cast<const float4*>(pcv + tt);
        float4 u4 = *reinterpret_cast<const float4*>(pu + tt);
        step(d4.x, b4.x, c4.x, u4.x, tt + 0);
        step(d4.y, b4.y, c4.y, u4.y, tt + 1);
        step(d4.z, b4.z, c4.z, u4.z, tt + 2);
        step(d4.w, b4.w, c4.w, u4.w, tt + 3);
    }

    if (j == CCH - 1 && carry != nullptr) {
        #pragma unroll
        for (int n = 0; n < 16; n++)
            carry[((size_t)b * GD + d) * GN_STATE + n] = x[n];
    }
}

// ---------------------------------------------------------------------------
extern "C" void kernel_launch(void* const* d_in, const int* in_sizes, int n_in,
                              void* d_out, int out_size) {
    const float* u      = (const float*)d_in[0];
    const float* Wdt    = (const float*)d_in[1];
    const float* bdt    = (const float*)d_in[2];
    const float* Wb     = (const float*)d_in[3];
    const float* bb     = (const float*)d_in[4];
    const float* Wc     = (const float*)d_in[5];
    const float* bc     = (const float*)d_in[6];
    const float* a_raw  = (const float*)d_in[7];
    const float* B_base = (const float*)d_in[8];
    const float* C_base = (const float*)d_in[9];
    const float* Dv     = (const float*)d_in[10];

    float* out = (float*)d_out;
    const long long y_elems = (long long)GB * GL * GD;
    float* carry = nullptr;
    float* y = out;
    if ((long long)out_size > y_elems) {
        carry = out;
        y = out + ((long long)out_size - y_elems);
    }

    cudaFuncSetAttribute(gemm_tc_kernel,
                         cudaFuncAttributeMaxDynamicSharedMemorySize, GEMM_SMEM);

    dim3 tgrid(GK / 32, GD / 32, 3);
    wtrans_kernel<<<tgrid, dim3(32, 8)>>>(Wdt, Wb, Wc);

    dim3 ugrid(GD / 32, GM / 32);
    uprep_kernel<<<ugrid, dim3(32, 8)>>>(u);

    dim3 ggrid(3 * (GD / 128), GM / 128);   // (48, 128)
    gemm_tc_kernel<<<ggrid, 256, GEMM_SMEM>>>(bdt, bb, bc);

    scanA_kernel<<<dim3(NCHAN / 128, CCH - 1), 128>>>(a_raw, B_base);
    scanC_kernel<<<NCHAN * GN_STATE / 256, 256>>>();
    scanB_kernel<<<dim3(NCHAN / 128, CCH), 128>>>(a_raw, B_base, C_base, Dv,
                                                  carry, y);
}

// round 15
// speedup vs baseline: 1.0814x; 1.0814x over previous
#include <cuda_runtime.h>
#include <cuda_fp16.h>
#include <cstdint>

// ---------------------------------------------------------------------------
// Problem constants
// ---------------------------------------------------------------------------
#define GB 4
#define GL 4096
#define GD 2048
#define GN_STATE 16
#define GM (GB*GL)          // 16384
#define GK GD               // 2048
#define DT_MIN 1e-4f
#define PLANE ((size_t)GM * GD)
#define NCHAN (GB * GD)     // 8192 channels
#define CCH 16              // scan chunks
#define TCH (GL / CCH)      // 256 steps per chunk

// Projections stored TRANSPOSED: [z][d][m]
__device__ float g_proj[3 * PLANE];
// Transposed fp16 weights: [z][d][k]
__device__ __half g_wth[(size_t)3 * GD * GK];
// fp16 u, GEMM orientation [m][k]
__device__ __half g_uph[PLANE];
// fp32 u, scan orientation [d][m]
__device__ float g_ut[PLANE];
// Scan chunk carries (in x' = x/Bb space)
__device__ float g_P [(CCH - 1) * NCHAN * GN_STATE];
__device__ float g_S [(CCH - 1) * NCHAN * GN_STATE];
__device__ float g_x0[CCH * NCHAN * GN_STATE];

__device__ __forceinline__ uint32_t smem_u32(const void* p) {
    uint32_t a;
    asm("{ .reg .u64 t; cvta.to.shared.u64 t, %1; cvt.u32.u64 %0, t; }" : "=r"(a) : "l"(p));
    return a;
}
__device__ __forceinline__ float softplus_f(float x) {
    return log1pf(expf(-fabsf(x))) + fmaxf(x, 0.0f);
}
__device__ __forceinline__ float ex2f(float x) {
    float r;
    asm("ex2.approx.ftz.f32 %0, %1;" : "=f"(r) : "f"(x));
    return r;
}
__device__ __forceinline__ void mma_f16(float c[4], const uint32_t a[4],
                                        uint32_t b0, uint32_t b1) {
    asm volatile(
        "mma.sync.aligned.m16n8k16.row.col.f32.f16.f16.f32 "
        "{%0,%1,%2,%3}, {%4,%5,%6,%7}, {%8,%9}, {%0,%1,%2,%3};\n"
        : "+f"(c[0]), "+f"(c[1]), "+f"(c[2]), "+f"(c[3])
        : "r"(a[0]), "r"(a[1]), "r"(a[2]), "r"(a[3]), "r"(b0), "r"(b1));
}
__device__ __forceinline__ void cp_async16(uint32_t dst, const void* src) {
    asm volatile("cp.async.cg.shared.global [%0], [%1], 16;" :: "r"(dst), "l"(src));
}
__device__ __forceinline__ void ldsm_x4(uint32_t& r0, uint32_t& r1,
                                        uint32_t& r2, uint32_t& r3, uint32_t a) {
    asm volatile("ldmatrix.sync.aligned.m8n8.x4.shared.b16 {%0,%1,%2,%3}, [%4];"
                 : "=r"(r0), "=r"(r1), "=r"(r2), "=r"(r3) : "r"(a));
}

// ---------------------------------------------------------------------------
// Prep: weight transpose + fp16 convert. g_wth[z][d][k] = half(W_z[k][d])
// ---------------------------------------------------------------------------
__global__ void wtrans_kernel(const float* __restrict__ Wdt,
                              const float* __restrict__ Wb,
                              const float* __restrict__ Wc) {
    __shared__ float t[32][33];
    const int z = blockIdx.z;
    const float* __restrict__ W = (z == 0) ? Wdt : ((z == 1) ? Wb : Wc);
    __half* __restrict__ out = g_wth + (size_t)z * GD * GK;
    const int k0 = blockIdx.x * 32, d0 = blockIdx.y * 32;
    for (int i = threadIdx.y; i < 32; i += 8)
        t[i][threadIdx.x] = W[(size_t)(k0 + i) * GD + d0 + threadIdx.x];
    __syncthreads();
    for (int i = threadIdx.y; i < 32; i += 8)
        out[(size_t)(d0 + i) * GK + k0 + threadIdx.x] =
            __float2half_rn(t[threadIdx.x][i]);
}

// ---------------------------------------------------------------------------
// Prep: u -> fp16 [m][k] for GEMM, fp32 transposed [d][m] for scan.
// ---------------------------------------------------------------------------
__global__ void uprep_kernel(const float* __restrict__ u) {
    __shared__ float t[32][33];
    const int d0 = blockIdx.x * 32, m0 = blockIdx.y * 32;
    for (int i = threadIdx.y; i < 32; i += 8) {
        float v = u[(size_t)(m0 + i) * GD + d0 + threadIdx.x];
        t[i][threadIdx.x] = v;
        g_uph[(size_t)(m0 + i) * GD + d0 + threadIdx.x] = __float2half_rn(v);
    }
    __syncthreads();
    for (int i = threadIdx.y; i < 32; i += 8)
        g_ut[(size_t)(d0 + i) * GM + m0 + threadIdx.x] = t[threadIdx.x][i];
}

// ---------------------------------------------------------------------------
// Pipelined fp16 GEMM with ldmatrix fragments (R11 configuration).
// Block 128(d=M) x 128(m=N), 256 threads (8 warps: 4 M x 2 N), warp 32x64.
// K-chunk 64 halves (4 x m16n8k16). 3-stage cp.async, 110,592 B smem,
// 2 blocks/SM. Row pitch 144 B -> conflict-free LDSM (offsets 16i mod 128).
// ---------------------------------------------------------------------------
#define KCH 64
#define PITCHB 144                    // 64 halves (128 B) + 16 B pad
#define A_BYTES (128 * PITCHB)        // 18432
#define B_BYTES (128 * PITCHB)        // 18432
#define STAGE_BYTES (A_BYTES + B_BYTES)   // 36864
#define GEMM_SMEM (3 * STAGE_BYTES)   // 110592
#define NCH (GK / KCH)                // 32

__global__ void __launch_bounds__(256, 2)
gemm_tc_kernel(const float* __restrict__ bdt, const float* __restrict__ bb,
               const float* __restrict__ bc) {
    extern __shared__ char smem[];

    const int tid = threadIdx.x;
    const int lane = tid & 31;
    const int warp = tid >> 5;
    const int z    = blockIdx.x >> 4;
    const int bd   = (blockIdx.x & 15) * 128;
    const int bm   = blockIdx.y * 128;
    const __half* __restrict__ W = g_wth + (size_t)z * GD * GK;
    const float* __restrict__ bias = (z == 0) ? bdt : ((z == 1) ? bb : bc);
    float* __restrict__ out = g_proj + (size_t)z * PLANE;

    const int wm = (warp & 3) * 32;     // 4 warps along M (d)
    const int wn = (warp >> 2) * 64;    // 2 warps along N (m)
    const int g  = lane >> 2;
    const int th = lane & 3;

    // Per-lane LDSM row/col offsets (loop-invariant).
    const int q = lane >> 3, i8 = lane & 7;
    const int a_row = wm + (q & 1) * 8 + i8;
    const int a_kb  = (q >> 1) * 16;
    const int b_rowo = (q >> 1) * 8 + i8;
    const int b_kb   = (q & 1) * 16;

    auto load_stage = [&](int c, int buf) {
        const int k0 = c * KCH;
        const uint32_t aB = smem_u32(smem + buf * STAGE_BYTES);
        const uint32_t bB = aB + A_BYTES;
        #pragma unroll
        for (int i = 0; i < 4; i++) {
            int lin = tid + i * 256;
            int row = lin >> 3, ch = lin & 7;
            cp_async16(aB + row * PITCHB + ch * 16,
                       W + (size_t)(bd + row) * GK + k0 + ch * 8);
        }
        #pragma unroll
        for (int i = 0; i < 4; i++) {
            int lin = tid + i * 256;
            int row = lin >> 3, ch = lin & 7;
            cp_async16(bB + row * PITCHB + ch * 16,
                       g_uph + (size_t)(bm + row) * GK + k0 + ch * 8);
        }
        asm volatile("cp.async.commit_group;" ::: "memory");
    };

    float acc[2][8][4];
    #pragma unroll
    for (int i = 0; i < 2; i++)
        #pragma unroll
        for (int j = 0; j < 8; j++)
            #pragma unroll
            for (int k = 0; k < 4; k++) acc[i][j][k] = 0.0f;

    load_stage(0, 0);
    load_stage(1, 1);

    for (int c = 0; c < NCH; c++) {
        const int buf = c % 3;
        if (c == NCH - 1)
            asm volatile("cp.async.wait_group 0;" ::: "memory");
        else
            asm volatile("cp.async.wait_group 1;" ::: "memory");
        __syncthreads();

        const uint32_t aS = smem_u32(smem + buf * STAGE_BYTES);
        const uint32_t bS = aS + A_BYTES;
        const uint32_t aLane = aS + a_row * PITCHB + a_kb;
        const uint32_t bLane = bS + (wn + b_rowo) * PITCHB + b_kb;

        #pragma unroll
        for (int kk = 0; kk < 4; kk++) {          // four m16n8k16 K-steps
            const uint32_t kb = kk * 32;
            uint32_t a[2][4];
            ldsm_x4(a[0][0], a[0][1], a[0][2], a[0][3], aLane + kb);
            ldsm_x4(a[1][0], a[1][1], a[1][2], a[1][3],
                    aLane + 16 * PITCHB + kb);
            uint32_t b[4][4];                      // [ntp][b0,b1 of nt, nt+1]
            #pragma unroll
            for (int ntp = 0; ntp < 4; ntp++)
                ldsm_x4(b[ntp][0], b[ntp][1], b[ntp][2], b[ntp][3],
                        bLane + (ntp * 16) * PITCHB + kb);
            #pragma unroll
            for (int ntp = 0; ntp < 4; ntp++) {
                mma_f16(acc[0][ntp * 2 + 0], a[0], b[ntp][0], b[ntp][1]);
                mma_f16(acc[1][ntp * 2 + 0], a[1], b[ntp][0], b[ntp][1]);
                mma_f16(acc[0][ntp * 2 + 1], a[0], b[ntp][2], b[ntp][3]);
                mma_f16(acc[1][ntp * 2 + 1], a[1], b[ntp][2], b[ntp][3]);
            }
        }
        if (c + 2 < NCH) load_stage(c + 2, (c + 2) % 3);
    }

    #pragma unroll
    for (int mt = 0; mt < 2; mt++) {
        #pragma unroll
        for (int e2 = 0; e2 < 2; e2++) {
            int r = bd + wm + mt * 16 + g + e2 * 8;
            float bv = bias[r];
            float* orow = out + (size_t)r * GM + bm;
            #pragma unroll
            for (int nt = 0; nt < 8; nt++) {
                int c0 = wn + nt * 8 + 2 * th;
                float2 v;
                v.x = acc[mt][nt][e2 * 2 + 0] + bv;
                v.y = acc[mt][nt][e2 * 2 + 1] + bv;
                if (z == 0) {
                    v.x = softplus_f(v.x) + DT_MIN;
                    v.y = softplus_f(v.y) + DT_MIN;
                }
                *reinterpret_cast<float2*>(orow + c0) = v;
            }
        }
    }
}

// ---------------------------------------------------------------------------
// Scan phase A (x' = x/Bb space): per (channel, chunk j<CCH-1):
//   S'[n] via S' = Abar*S' + w  (w scalar), P[n] = exp2(kA[n] * sum(dts)).
// 49 issue slots/step: 16 ex2 + 16 argmul + 16 fma + 1 add. No B_base needed.
// ---------------------------------------------------------------------------
__global__ void __launch_bounds__(128)
scanA_kernel(const float* __restrict__ a_raw) {
    const int ch = blockIdx.x * 128 + threadIdx.x;
    const int j  = blockIdx.y;
    const int b = ch >> 11, d = ch & 2047;

    float kA[16], S[16];
    #pragma unroll
    for (int n = 0; n < 16; n++) {
        kA[n] = -softplus_f(a_raw[d * GN_STATE + n]) * 1.4426950408889634f;
        S[n] = 0.0f;
    }
    float dsum = 0.0f;

    const size_t sbase = (size_t)d * GM + (size_t)b * GL + (size_t)j * TCH;
    const float* __restrict__ pdt = g_proj + sbase;
    const float* __restrict__ pbv = g_proj + PLANE + sbase;
    const float* __restrict__ pu  = g_ut + sbase;

    auto step = [&](float dts, float bs, float us) {
        const float w = dts * bs * us;
        dsum += dts;
        #pragma unroll
        for (int n = 0; n < 16; n++) {
            float Abar = ex2f(dts * kA[n]);
            S[n] = fmaf(Abar, S[n], w);
        }
    };

    for (int tt = 0; tt < TCH; tt += 4) {
        float4 d4 = *reinterpret_cast<const float4*>(pdt + tt);
        float4 b4 = *reinterpret_cast<const float4*>(pbv + tt);
        float4 u4 = *reinterpret_cast<const float4*>(pu + tt);
        step(d4.x, b4.x, u4.x);
        step(d4.y, b4.y, u4.y);
        step(d4.z, b4.z, u4.z);
        step(d4.w, b4.w, u4.w);
    }

    const int o = (j * NCHAN + ch) * GN_STATE;
    #pragma unroll
    for (int n = 0; n < 16; n++) {
        g_P[o + n] = ex2f(kA[n] * dsum);
        g_S[o + n] = S[n];
    }
}

// ---------------------------------------------------------------------------
// Scan combine (x' space): x0(0)=0; x0(j)=S(j-1)+P(j-1)*x0(j-1)
// ---------------------------------------------------------------------------
__global__ void __launch_bounds__(256)
scanC_kernel() {
    const int id = blockIdx.x * 256 + threadIdx.x;   // 0 .. NCHAN*16-1
    float x = 0.0f;
    g_x0[id] = 0.0f;
    #pragma unroll
    for (int j = 1; j < CCH; j++) {
        const int o = (j - 1) * NCHAN * GN_STATE + id;
        x = g_S[o] + g_P[o] * x;
        g_x0[j * NCHAN * GN_STATE + id] = x;
    }
}

// ---------------------------------------------------------------------------
// Scan phase B (x' space): full walk per chunk with known x0'; emits
// y = cs * sum(CB[n]*x'[n]) + Dd*us, CB = Cb*Bb. Carry rescales once.
// ---------------------------------------------------------------------------
__global__ void __launch_bounds__(128)
scanB_kernel(const float* __restrict__ a_raw, const float* __restrict__ B_base,
             const float* __restrict__ C_base, const float* __restrict__ Dv,
             float* __restrict__ carry, float* __restrict__ y) {
    const int ch = blockIdx.x * 128 + threadIdx.x;
    const int j  = blockIdx.y;
    const int b = ch >> 11, d = ch & 2047;

    float kA[16], CB[16], x[16];
    #pragma unroll
    for (int n = 0; n < 16; n++) {
        kA[n] = -softplus_f(a_raw[d * GN_STATE + n]) * 1.4426950408889634f;
        CB[n] = C_base[d * GN_STATE + n] * B_base[d * GN_STATE + n];
        x[n]  = g_x0[(j * NCHAN + ch) * GN_STATE + n];
    }
    const float Dd = Dv[d];

    const size_t sbase = (size_t)d * GM + (size_t)b * GL + (size_t)j * TCH;
    const float* __restrict__ pdt = g_proj + sbase;
    const float* __restrict__ pbv = g_proj + PLANE + sbase;
    const float* __restrict__ pcv = g_proj + 2 * PLANE + sbase;
    const float* __restrict__ pu  = g_ut + sbase;
    float* __restrict__ yb = y + ((size_t)b * GL + (size_t)j * TCH) * GD + d;

    auto step = [&](float dts, float bs, float cs, float us, int t) {
        const float w = dts * bs * us;
        float acc = 0.0f;
        #pragma unroll
        for (int n = 0; n < 16; n++) {
            float Abar = ex2f(dts * kA[n]);
            x[n] = fmaf(Abar, x[n], w);
            acc = fmaf(x[n], CB[n], acc);
        }
        yb[(size_t)t * GD] = fmaf(cs, acc, Dd * us);
    };

    for (int tt = 0; tt < TCH; tt += 4) {
        float4 d4 = *reinterpret_cast<const float4*>(pdt + tt);
        float4 b4 = *reinterpret_cast<const float4*>(pbv + tt);
        float4 c4 = *reinterpret_cast<const float4*>(pcv + tt);
        float4 u4 = *reinterpret_cast<const float4*>(pu + tt);
        step(d4.x, b4.x, c4.x, u4.x, tt + 0);
        step(d4.y, b4.y, c4.y, u4.y, tt + 1);
        step(d4.z, b4.z, c4.z, u4.z, tt + 2);
        step(d4.w, b4.w, c4.w, u4.w, tt + 3);
    }

    if (j == CCH - 1 && carry != nullptr) {
        #pragma unroll
        for (int n = 0; n < 16; n++)
            carry[((size_t)b * GD + d) * GN_STATE + n] =
                x[n] * B_base[d * GN_STATE + n];
    }
}

// ---------------------------------------------------------------------------
extern "C" void kernel_launch(void* const* d_in, const int* in_sizes, int n_in,
                              void* d_out, int out_size) {
    const float* u      = (const float*)d_in[0];
    const float* Wdt    = (const float*)d_in[1];
    const float* bdt    = (const float*)d_in[2];
    const float* Wb     = (const float*)d_in[3];
    const float* bb     = (const float*)d_in[4];
    const float* Wc     = (const float*)d_in[5];
    const float* bc     = (const float*)d_in[6];
    const float* a_raw  = (const float*)d_in[7];
    const float* B_base = (const float*)d_in[8];
    const float* C_base = (const float*)d_in[9];
    const float* Dv     = (const float*)d_in[10];

    float* out = (float*)d_out;
    const long long y_elems = (long long)GB * GL * GD;
    float* carry = nullptr;
    float* y = out;
    if ((long long)out_size > y_elems) {
        carry = out;
        y = out + ((long long)out_size - y_elems);
    }

    cudaFuncSetAttribute(gemm_tc_kernel,
                         cudaFuncAttributeMaxDynamicSharedMemorySize, GEMM_SMEM);

    dim3 tgrid(GK / 32, GD / 32, 3);
    wtrans_kernel<<<tgrid, dim3(32, 8)>>>(Wdt, Wb, Wc);

    dim3 ugrid(GD / 32, GM / 32);
    uprep_kernel<<<ugrid, dim3(32, 8)>>>(u);

    dim3 ggrid(3 * (GD / 128), GM / 128);   // (48, 128)
    gemm_tc_kernel<<<ggrid, 256, GEMM_SMEM>>>(bdt, bb, bc);

    scanA_kernel<<<dim3(NCHAN / 128, CCH - 1), 128>>>(a_raw);
    scanC_kernel<<<NCHAN * GN_STATE / 256, 256>>>();
    scanB_kernel<<<dim3(NCHAN / 128, CCH), 128>>>(a_raw, B_base, C_base, Dv,
                                                  carry, y);
}